// round 2
// baseline (speedup 1.0000x reference)
#include <cuda_runtime.h>
#include <cuda_bf16.h>

#define N_NODES_MAX 100000
#define HIDDEN 64

// Per-node precomputed projections: u = z @ W1[0:64,:], v = z @ W1[64:128,:]
__device__ float g_u[N_NODES_MAX * HIDDEN];
__device__ float g_v[N_NODES_MAX * HIDDEN];
__device__ int   g_idx_is64;   // 1 if edge_index buffer is int64, 0 if int32

// ---------------------------------------------------------------------------
// Detect edge_index dtype. If data is int64 (values < 2^31), every odd int32
// word is zero. Check 128 odd words: any nonzero -> int32.
// ---------------------------------------------------------------------------
__global__ void detect_idx_dtype_kernel(const int* __restrict__ ei_as_i32) {
    if (threadIdx.x == 0 && blockIdx.x == 0) {
        int is64 = 1;
        #pragma unroll 4
        for (int i = 0; i < 128; i++) {
            if (ei_as_i32[2 * i + 1] != 0) { is64 = 0; break; }
        }
        g_idx_is64 = is64;
    }
}

// ---------------------------------------------------------------------------
// Precompute kernel: 256 threads, 2 nodes per iteration.
// thread t: sub = t>>7 selects node within pair, k = t&127 selects output col
// (k<64 -> u column k, k>=64 -> v column k-64). W column held in registers.
// ---------------------------------------------------------------------------
__global__ void precompute_uv_kernel(const float* __restrict__ z,
                                     const float* __restrict__ W1,
                                     int n_nodes) {
    __shared__ float zs[2][HIDDEN];
    const int tid = threadIdx.x;
    const int sub = tid >> 7;          // 0 or 1
    const int k   = tid & 127;         // 0..127

    // Load this thread's W1 column into registers.
    float w[HIDDEN];
    #pragma unroll
    for (int j = 0; j < HIDDEN; j++) {
        w[j] = (k < HIDDEN) ? W1[j * HIDDEN + k]
                            : W1[(HIDDEN + j) * HIDDEN + (k - HIDDEN)];
    }
    float* dst = (k < HIDDEN) ? g_u : g_v;
    const int kk = k & (HIDDEN - 1);

    for (int base = blockIdx.x * 2; base < n_nodes; base += gridDim.x * 2) {
        __syncthreads();
        if (tid < 128) {
            const int nn = base + (tid >> 6);
            zs[tid >> 6][tid & 63] = (nn < n_nodes) ? z[nn * HIDDEN + (tid & 63)] : 0.f;
        }
        __syncthreads();
        const int n = base + sub;
        if (n < n_nodes) {
            const float* zr = zs[sub];
            float acc = 0.f;
            #pragma unroll
            for (int j = 0; j < HIDDEN; j++) acc = fmaf(zr[j], w[j], acc);
            dst[n * HIDDEN + kk] = acc;
        }
    }
}

// ---------------------------------------------------------------------------
// Edge kernel: 8 lanes per edge (4 edges per warp).
// Lane j (0..7) of each octet covers columns {4j..4j+3} U {32+4j..32+4j+3}
// via two coalesced float4 loads from each of u[row], v[col].
// ---------------------------------------------------------------------------
__global__ void edge_decode_kernel(const void* __restrict__ ei_raw,
                                   const float* __restrict__ b1,
                                   const float* __restrict__ W2,
                                   const float* __restrict__ b2,
                                   float* __restrict__ out,
                                   int n_edges) {
    const int lane = threadIdx.x & 31;
    const int oct  = lane >> 3;    // edge slot within the warp (0..3)
    const int j    = lane & 7;     // lane within octet (0..7)

    const int is64 = g_idx_is64;
    const long long* __restrict__ ei64 = (const long long*)ei_raw;
    const int*       __restrict__ ei32 = (const int*)ei_raw;

    const float4* __restrict__ B1  = (const float4*)b1;
    const float4* __restrict__ W2v = (const float4*)W2;
    const float4 b1a = B1[j];
    const float4 b1b = B1[8 + j];
    const float4 w2a = W2v[j];
    const float4 w2b = W2v[8 + j];
    const float bias2 = b2[0];

    const float4* __restrict__ U = (const float4*)g_u;
    const float4* __restrict__ V = (const float4*)g_v;

    const long long warp_global =
        (long long)((blockIdx.x * blockDim.x + threadIdx.x) >> 5);
    const long long stride = ((long long)gridDim.x * blockDim.x) >> 5;

    for (long long e = warp_global * 4 + oct; e < n_edges; e += stride * 4) {
        long long r, c;
        if (is64) {
            r = ei64[e];
            c = ei64[(long long)n_edges + e];
        } else {
            r = ei32[e];
            c = ei32[(long long)n_edges + e];
        }

        const float4 ua = U[r * 16 + j];
        const float4 ub = U[r * 16 + 8 + j];
        const float4 va = V[c * 16 + j];
        const float4 vb = V[c * 16 + 8 + j];

        float s = 0.f;
        s = fmaf(fmaxf(ua.x + va.x + b1a.x, 0.f), w2a.x, s);
        s = fmaf(fmaxf(ua.y + va.y + b1a.y, 0.f), w2a.y, s);
        s = fmaf(fmaxf(ua.z + va.z + b1a.z, 0.f), w2a.z, s);
        s = fmaf(fmaxf(ua.w + va.w + b1a.w, 0.f), w2a.w, s);
        s = fmaf(fmaxf(ub.x + vb.x + b1b.x, 0.f), w2b.x, s);
        s = fmaf(fmaxf(ub.y + vb.y + b1b.y, 0.f), w2b.y, s);
        s = fmaf(fmaxf(ub.z + vb.z + b1b.z, 0.f), w2b.z, s);
        s = fmaf(fmaxf(ub.w + vb.w + b1b.w, 0.f), w2b.w, s);

        // reduce across the 8-lane octet
        s += __shfl_xor_sync(0xffffffffu, s, 1);
        s += __shfl_xor_sync(0xffffffffu, s, 2);
        s += __shfl_xor_sync(0xffffffffu, s, 4);

        if (j == 0) out[e] = s + bias2;
    }
}

// ---------------------------------------------------------------------------
// Launch. Input order (metadata): z, edge_index [2,E], W1, b1, W2, b2.
// Output: float32 [E, 1].
// ---------------------------------------------------------------------------
extern "C" void kernel_launch(void* const* d_in, const int* in_sizes, int n_in,
                              void* d_out, int out_size) {
    const float* z  = (const float*)d_in[0];
    const void*  ei = d_in[1];
    const float* W1 = (const float*)d_in[2];
    const float* b1 = (const float*)d_in[3];
    const float* W2 = (const float*)d_in[4];
    const float* b2 = (const float*)d_in[5];
    float* out = (float*)d_out;

    const int n_nodes = in_sizes[0] / HIDDEN;
    const int n_edges = in_sizes[1] / 2;

    // Phase 0: detect index dtype (device-side, graph-capturable).
    detect_idx_dtype_kernel<<<1, 32>>>((const int*)ei);

    // Phase 1: per-node projections into L2-resident scratch.
    {
        const int threads = 256;
        int blocks = (n_nodes + 1) / 2;
        if (blocks > 1184) blocks = 1184;   // 148 SMs * 8
        precompute_uv_kernel<<<blocks, threads>>>(z, W1, n_nodes);
    }

    // Phase 2: edge decode. 32 edges per 256-thread block.
    {
        const int threads = 256;
        const int edges_per_block = 32;
        const int blocks = (n_edges + edges_per_block - 1) / edges_per_block;
        edge_decode_kernel<<<blocks, threads>>>(ei, b1, W2, b2, out, n_edges);
    }
}

// round 3
// speedup vs baseline: 1.3769x; 1.3769x over previous
#include <cuda_runtime.h>
#include <cuda_fp16.h>
#include <cuda_bf16.h>

#define N_NODES_MAX 100000
#define HIDDEN 64

// Per-node precomputed projections in fp16:
//   u = z @ W1[0:64,:], v = z @ W1[64:128,:]
// Stored as uint4 (8 halves) for guaranteed 16B alignment: 8 uint4 per node.
__device__ uint4 g_u[N_NODES_MAX * 8];
__device__ uint4 g_v[N_NODES_MAX * 8];
__device__ int   g_idx_is64;   // 1 if edge_index buffer is int64, 0 if int32

// ---------------------------------------------------------------------------
// Detect edge_index dtype. If data is int64 (values < 2^31), every odd int32
// word is zero. 128 threads each check one odd word; ballot-reduce.
// ---------------------------------------------------------------------------
__global__ void detect_idx_dtype_kernel(const int* __restrict__ ei_as_i32) {
    const int t = threadIdx.x;                 // 0..127
    int nz = (ei_as_i32[2 * t + 1] != 0) ? 1 : 0;
    __shared__ int s_nz[4];
    unsigned b = __ballot_sync(0xffffffffu, nz);
    if ((t & 31) == 0) s_nz[t >> 5] = (b != 0);
    __syncthreads();
    if (t == 0) g_idx_is64 = !(s_nz[0] | s_nz[1] | s_nz[2] | s_nz[3]);
}

// ---------------------------------------------------------------------------
// Precompute kernel: 256 threads, 2 nodes per iteration.
// thread t: sub = t>>7 selects node within pair, k = t&127 selects output col
// (k<64 -> u column k, k>=64 -> v column k-64). W column held in registers.
// ---------------------------------------------------------------------------
__global__ void precompute_uv_kernel(const float* __restrict__ z,
                                     const float* __restrict__ W1,
                                     int n_nodes) {
    __shared__ float zs[2][HIDDEN];
    const int tid = threadIdx.x;
    const int sub = tid >> 7;          // 0 or 1
    const int k   = tid & 127;         // 0..127

    float w[HIDDEN];
    #pragma unroll
    for (int j = 0; j < HIDDEN; j++) {
        w[j] = (k < HIDDEN) ? W1[j * HIDDEN + k]
                            : W1[(HIDDEN + j) * HIDDEN + (k - HIDDEN)];
    }
    __half* dst = (k < HIDDEN) ? (__half*)g_u : (__half*)g_v;
    const int kk = k & (HIDDEN - 1);

    for (int base = blockIdx.x * 2; base < n_nodes; base += gridDim.x * 2) {
        __syncthreads();
        if (tid < 128) {
            const int nn = base + (tid >> 6);
            zs[tid >> 6][tid & 63] = (nn < n_nodes) ? z[nn * HIDDEN + (tid & 63)] : 0.f;
        }
        __syncthreads();
        const int n = base + sub;
        if (n < n_nodes) {
            const float* zr = zs[sub];
            float acc = 0.f;
            #pragma unroll
            for (int j = 0; j < HIDDEN; j++) acc = fmaf(zr[j], w[j], acc);
            dst[n * HIDDEN + kk] = __float2half_rn(acc);
        }
    }
}

// ---------------------------------------------------------------------------
// Edge math helper: one lane's 8-column partial dot for one edge.
// ---------------------------------------------------------------------------
__device__ __forceinline__ float oct_partial(uint4 u, uint4 v,
                                             const float* __restrict__ bb,
                                             const float* __restrict__ ww) {
    const __half2* up = (const __half2*)&u;
    const __half2* vp = (const __half2*)&v;
    float s = 0.f;
    #pragma unroll
    for (int i = 0; i < 4; i++) {
        float2 a = __half22float2(up[i]);
        float2 b = __half22float2(vp[i]);
        s = fmaf(fmaxf(a.x + b.x + bb[2 * i],     0.f), ww[2 * i],     s);
        s = fmaf(fmaxf(a.y + b.y + bb[2 * i + 1], 0.f), ww[2 * i + 1], s);
    }
    return s;
}

// ---------------------------------------------------------------------------
// Edge kernel: 8 lanes per edge, 2 edges per octet per iteration
// (8 edges per warp). Lane j covers columns 8j..8j+7 via one 16B load from
// each of u[row], v[col] per edge.
// ---------------------------------------------------------------------------
__global__ void edge_decode_kernel(const void* __restrict__ ei_raw,
                                   const float* __restrict__ b1,
                                   const float* __restrict__ W2,
                                   const float* __restrict__ b2,
                                   float* __restrict__ out,
                                   int n_edges) {
    const int lane = threadIdx.x & 31;
    const int oct  = lane >> 3;    // edge slot within warp (0..3)
    const int j    = lane & 7;     // lane within octet (0..7)

    const int is64 = g_idx_is64;
    const long long* __restrict__ ei64 = (const long long*)ei_raw;
    const int*       __restrict__ ei32 = (const int*)ei_raw;

    float bb[8], ww[8];
    #pragma unroll
    for (int i = 0; i < 8; i++) {
        bb[i] = b1[8 * j + i];
        ww[i] = W2[8 * j + i];
    }
    const float bias2 = b2[0];

    const long long warp_global =
        (long long)((blockIdx.x * blockDim.x + threadIdx.x) >> 5);
    const long long warp_stride = ((long long)gridDim.x * blockDim.x) >> 5;

    for (long long base = warp_global * 8; base < n_edges;
         base += warp_stride * 8) {
        const long long e0 = base + oct;
        const long long e1 = base + 4 + oct;
        const bool has0 = e0 < n_edges;
        const bool has1 = e1 < n_edges;

        long long r0 = 0, c0 = 0, r1 = 0, c1 = 0;
        if (is64) {
            if (has0) { r0 = ei64[e0]; c0 = ei64[(long long)n_edges + e0]; }
            if (has1) { r1 = ei64[e1]; c1 = ei64[(long long)n_edges + e1]; }
        } else {
            if (has0) { r0 = ei32[e0]; c0 = ei32[(long long)n_edges + e0]; }
            if (has1) { r1 = ei32[e1]; c1 = ei32[(long long)n_edges + e1]; }
        }

        uint4 ua0, va0, ua1, va1;
        if (has0) { ua0 = g_u[r0 * 8 + j]; va0 = g_v[c0 * 8 + j]; }
        if (has1) { ua1 = g_u[r1 * 8 + j]; va1 = g_v[c1 * 8 + j]; }

        float s0 = has0 ? oct_partial(ua0, va0, bb, ww) : 0.f;
        float s1 = has1 ? oct_partial(ua1, va1, bb, ww) : 0.f;

        s0 += __shfl_xor_sync(0xffffffffu, s0, 1);
        s1 += __shfl_xor_sync(0xffffffffu, s1, 1);
        s0 += __shfl_xor_sync(0xffffffffu, s0, 2);
        s1 += __shfl_xor_sync(0xffffffffu, s1, 2);
        s0 += __shfl_xor_sync(0xffffffffu, s0, 4);
        s1 += __shfl_xor_sync(0xffffffffu, s1, 4);

        if (j == 0) {
            if (has0) out[e0] = s0 + bias2;
            if (has1) out[e1] = s1 + bias2;
        }
    }
}

// ---------------------------------------------------------------------------
// Launch. Input order (metadata): z, edge_index [2,E], W1, b1, W2, b2.
// Output: float32 [E, 1].
// ---------------------------------------------------------------------------
extern "C" void kernel_launch(void* const* d_in, const int* in_sizes, int n_in,
                              void* d_out, int out_size) {
    const float* z  = (const float*)d_in[0];
    const void*  ei = d_in[1];
    const float* W1 = (const float*)d_in[2];
    const float* b1 = (const float*)d_in[3];
    const float* W2 = (const float*)d_in[4];
    const float* b2 = (const float*)d_in[5];
    float* out = (float*)d_out;

    const int n_nodes = in_sizes[0] / HIDDEN;
    const int n_edges = in_sizes[1] / 2;

    // Phase 0: detect index dtype (device-side, graph-capturable).
    detect_idx_dtype_kernel<<<1, 128>>>((const int*)ei);

    // Phase 1: per-node fp16 projections into L2-resident scratch.
    {
        const int threads = 256;
        int blocks = (n_nodes + 1) / 2;
        if (blocks > 1184) blocks = 1184;   // 148 SMs * 8
        precompute_uv_kernel<<<blocks, threads>>>(z, W1, n_nodes);
    }

    // Phase 2: edge decode. 8 warps/block, 8 edges/warp -> 64 edges/block.
    {
        const int threads = 256;
        const int edges_per_block = 64;
        const int blocks = (n_edges + edges_per_block - 1) / edges_per_block;
        edge_decode_kernel<<<blocks, threads>>>(ei, b1, W2, b2, out, n_edges);
    }
}

// round 4
// speedup vs baseline: 1.9911x; 1.4461x over previous
#include <cuda_runtime.h>
#include <cuda_fp16.h>
#include <cuda_bf16.h>

#define N_NODES_MAX 100000
#define HIDDEN 64

// Per-node precomputed fp16 projections:
//   u = z @ W1[0:64,:], v = z @ W1[64:128,:]
// Stored as uint4 (8 halves each): 8 uint4 per node = 128 B.
__device__ uint4 g_u[N_NODES_MAX * 8];
__device__ uint4 g_v[N_NODES_MAX * 8];
__device__ int   g_idx_is64;   // 1 if edge_index buffer is int64, 0 if int32

// ---------------------------------------------------------------------------
// Precompute kernel: 256 threads, 2 nodes per iteration.
// Block 0 additionally detects the edge_index dtype (int64 data has all-zero
// odd int32 words since indices < 2^31).
// ---------------------------------------------------------------------------
__global__ void precompute_uv_kernel(const float* __restrict__ z,
                                     const float* __restrict__ W1,
                                     const int* __restrict__ ei_as_i32,
                                     int n_nodes) {
    __shared__ float zs[2][HIDDEN];
    __shared__ int s_nz[4];
    const int tid = threadIdx.x;

    // --- dtype detection (block 0 only; warps 0-3 fully active) ---
    if (blockIdx.x == 0) {
        if (tid < 128) {
            int nz = (ei_as_i32[2 * tid + 1] != 0) ? 1 : 0;
            unsigned b = __ballot_sync(0xffffffffu, nz);
            if ((tid & 31) == 0) s_nz[tid >> 5] = (b != 0);
        }
        __syncthreads();
        if (tid == 0)
            g_idx_is64 = !(s_nz[0] | s_nz[1] | s_nz[2] | s_nz[3]);
    }

    const int sub = tid >> 7;          // 0 or 1
    const int k   = tid & 127;         // 0..127

    // This thread's W1 column in registers.
    float w[HIDDEN];
    #pragma unroll
    for (int j = 0; j < HIDDEN; j++) {
        w[j] = (k < HIDDEN) ? W1[j * HIDDEN + k]
                            : W1[(HIDDEN + j) * HIDDEN + (k - HIDDEN)];
    }
    __half* dst = (k < HIDDEN) ? (__half*)g_u : (__half*)g_v;
    const int kk = k & (HIDDEN - 1);

    for (int base = blockIdx.x * 2; base < n_nodes; base += gridDim.x * 2) {
        __syncthreads();
        if (tid < 128) {
            const int nn = base + (tid >> 6);
            zs[tid >> 6][tid & 63] = (nn < n_nodes) ? z[nn * HIDDEN + (tid & 63)] : 0.f;
        }
        __syncthreads();
        const int n = base + sub;
        if (n < n_nodes) {
            const float* zr = zs[sub];
            float acc = 0.f;
            #pragma unroll
            for (int j = 0; j < HIDDEN; j++) acc = fmaf(zr[j], w[j], acc);
            dst[n * HIDDEN + kk] = __float2half_rn(acc);
        }
    }
}

// ---------------------------------------------------------------------------
// One lane's 8-column partial dot for one edge.
// ---------------------------------------------------------------------------
__device__ __forceinline__ float oct_partial(uint4 u, uint4 v,
                                             const float* __restrict__ bb,
                                             const float* __restrict__ ww) {
    const __half2* up = (const __half2*)&u;
    const __half2* vp = (const __half2*)&v;
    float s = 0.f;
    #pragma unroll
    for (int i = 0; i < 4; i++) {
        float2 a = __half22float2(up[i]);
        float2 b = __half22float2(vp[i]);
        s = fmaf(fmaxf(a.x + b.x + bb[2 * i],     0.f), ww[2 * i],     s);
        s = fmaf(fmaxf(a.y + b.y + bb[2 * i + 1], 0.f), ww[2 * i + 1], s);
    }
    return s;
}

// ---------------------------------------------------------------------------
// Edge kernel: each warp handles 32 edges.
//   Phase A: lane l loads indices of edge base+l (coalesced; 2 LDG / 32 edges).
//   Phase B: 8 fully-unrolled substeps x 4 edges; 8 lanes per edge gather one
//            16B chunk each of u[row], v[col]. All 16 value loads per lane are
//            independent -> high MLP, L2 latency hidden.
// ---------------------------------------------------------------------------
__global__ __launch_bounds__(256)
void edge_decode_kernel(const void* __restrict__ ei_raw,
                        const float* __restrict__ b1,
                        const float* __restrict__ W2,
                        const float* __restrict__ b2,
                        float* __restrict__ out,
                        int n_edges) {
    const int lane = threadIdx.x & 31;
    const int oct  = lane >> 3;    // edge slot within substep (0..3)
    const int j    = lane & 7;     // lane within octet (0..7)

    const long long base =
        (long long)((blockIdx.x * blockDim.x + threadIdx.x) >> 5) * 32;
    if (base >= n_edges) return;

    const int is64 = g_idx_is64;
    const long long* __restrict__ ei64 = (const long long*)ei_raw;
    const int*       __restrict__ ei32 = (const int*)ei_raw;

    // Coalesced per-warp index load: lane l -> edge base+l.
    const long long eL = base + lane;
    const bool haveL = eL < n_edges;
    int r_all, c_all;
    if (is64) {
        r_all = haveL ? (int)ei64[eL] : 0;
        c_all = haveL ? (int)ei64[(long long)n_edges + eL] : 0;
    } else {
        r_all = haveL ? ei32[eL] : 0;
        c_all = haveL ? ei32[(long long)n_edges + eL] : 0;
    }

    float bb[8], ww[8];
    #pragma unroll
    for (int i = 0; i < 8; i++) {
        bb[i] = b1[8 * j + i];
        ww[i] = W2[8 * j + i];
    }
    const float bias2 = b2[0];

    const bool full_tile = (base + 32) <= (long long)n_edges;

    #pragma unroll
    for (int s = 0; s < 8; s++) {
        const int e_off = s * 4 + oct;                        // 0..31
        const int r = __shfl_sync(0xffffffffu, r_all, e_off);
        const int c = __shfl_sync(0xffffffffu, c_all, e_off);

        const uint4 u = g_u[(size_t)r * 8 + j];
        const uint4 v = g_v[(size_t)c * 8 + j];

        float acc = oct_partial(u, v, bb, ww);
        acc += __shfl_xor_sync(0xffffffffu, acc, 1);
        acc += __shfl_xor_sync(0xffffffffu, acc, 2);
        acc += __shfl_xor_sync(0xffffffffu, acc, 4);

        if (j == 0) {
            const long long e = base + e_off;
            if (full_tile || e < n_edges) out[e] = acc + bias2;
        }
    }
}

// ---------------------------------------------------------------------------
// Launch. Input order (metadata): z, edge_index [2,E], W1, b1, W2, b2.
// Output: float32 [E, 1].
// ---------------------------------------------------------------------------
extern "C" void kernel_launch(void* const* d_in, const int* in_sizes, int n_in,
                              void* d_out, int out_size) {
    const float* z  = (const float*)d_in[0];
    const void*  ei = d_in[1];
    const float* W1 = (const float*)d_in[2];
    const float* b1 = (const float*)d_in[3];
    const float* W2 = (const float*)d_in[4];
    const float* b2 = (const float*)d_in[5];
    float* out = (float*)d_out;

    const int n_nodes = in_sizes[0] / HIDDEN;
    const int n_edges = in_sizes[1] / 2;

    // Phase 1: per-node fp16 projections (+ dtype detect in block 0).
    {
        const int threads = 256;
        int blocks = (n_nodes + 1) / 2;
        if (blocks > 1184) blocks = 1184;   // 148 SMs * 8
        precompute_uv_kernel<<<blocks, threads>>>(z, W1, (const int*)ei, n_nodes);
    }

    // Phase 2: edge decode. 8 warps/block, 32 edges/warp -> 256 edges/block.
    {
        const int threads = 256;
        const int edges_per_block = 256;
        const int blocks = (n_edges + edges_per_block - 1) / edges_per_block;
        edge_decode_kernel<<<blocks, threads>>>(ei, b1, W2, b2, out, n_edges);
    }
}

// round 5
// speedup vs baseline: 2.7695x; 1.3909x over previous
#include <cuda_runtime.h>
#include <cuda_fp16.h>
#include <cuda_bf16.h>

#define N_NODES_MAX 100000
#define HIDDEN 64

// Per-node precomputed fp16 projections:
//   u = z @ W1[0:64,:], v = z @ W1[64:128,:]
// 8 uint4 (= 64 halves = 128 B) per node per array.
__device__ uint4 g_u[N_NODES_MAX * 8];
__device__ uint4 g_v[N_NODES_MAX * 8];
__device__ int   g_idx_is64;   // 1 if edge_index buffer is int64

// ---------------------------------------------------------------------------
// Precompute: thread = node. z row (64 f32) in registers; transposed combined
// weight Wt[n][k] (n=0..127 output col, k=0..63) staged in smem, read via
// broadcast LDS.128 (1 LDS per 4 FMA). Block 0 also detects index dtype.
// ---------------------------------------------------------------------------
__global__ __launch_bounds__(256)
void precompute_uv_kernel(const float* __restrict__ z,
                          const float* __restrict__ W1,
                          const int* __restrict__ ei_as_i32,
                          int n_nodes) {
    __shared__ float wt[128][HIDDEN];   // 32 KB: Wt[n][k]
    __shared__ int s_nz[4];
    const int tid = threadIdx.x;

    // dtype detection (block 0, warps 0-3)
    if (blockIdx.x == 0) {
        if (tid < 128) {
            int nz = (ei_as_i32[2 * tid + 1] != 0) ? 1 : 0;
            unsigned b = __ballot_sync(0xffffffffu, nz);
            if ((tid & 31) == 0) s_nz[tid >> 5] = (b != 0);
        }
        if (tid == 0) {
            __threadfence_block();
        }
    }

    // Stage transposed weights: W1 is [128][64] row-major.
    //   n<64 : Wt[n][k]      = W1[k][n]        (u part)
    //   n>=64: Wt[64+m][k]   = W1[64+k][m]     (v part)
    for (int i = tid; i < 128 * HIDDEN; i += 256) {
        const int j = i >> 6;       // W1 row 0..127
        const int m = i & 63;       // W1 col 0..63
        const float val = W1[i];
        if (j < HIDDEN) wt[m][j] = val;
        else            wt[HIDDEN + m][j - HIDDEN] = val;
    }
    __syncthreads();

    if (blockIdx.x == 0 && tid == 0)
        g_idx_is64 = !(s_nz[0] | s_nz[1] | s_nz[2] | s_nz[3]);

    const int node = blockIdx.x * 256 + tid;
    if (node >= n_nodes) return;

    // z row into registers (16 x float4)
    float zr[HIDDEN];
    {
        const float4* zp = (const float4*)(z + (size_t)node * HIDDEN);
        #pragma unroll
        for (int i = 0; i < 16; i++) ((float4*)zr)[i] = zp[i];
    }

    // 16 chunks of 8 output columns each; one uint4 (8 halves) store per chunk.
    for (int n0 = 0; n0 < 128; n0 += 8) {
        float acc[8];
        #pragma unroll
        for (int c = 0; c < 8; c++) acc[c] = 0.f;

        #pragma unroll
        for (int k0 = 0; k0 < HIDDEN; k0 += 4) {
            #pragma unroll
            for (int c = 0; c < 8; c++) {
                const float4 b = *(const float4*)&wt[n0 + c][k0];
                acc[c] = fmaf(b.x, zr[k0],     acc[c]);
                acc[c] = fmaf(b.y, zr[k0 + 1], acc[c]);
                acc[c] = fmaf(b.z, zr[k0 + 2], acc[c]);
                acc[c] = fmaf(b.w, zr[k0 + 3], acc[c]);
            }
        }

        uint4 pack;
        __half2* hp = (__half2*)&pack;
        #pragma unroll
        for (int c = 0; c < 4; c++)
            hp[c] = __floats2half2_rn(acc[2 * c], acc[2 * c + 1]);

        if (n0 < HIDDEN) g_u[(size_t)node * 8 + (n0 >> 3)] = pack;
        else             g_v[(size_t)node * 8 + ((n0 - HIDDEN) >> 3)] = pack;
    }
}

// ---------------------------------------------------------------------------
// One lane's 8-column partial dot: half2 add/add/relu, fp32 dot.
// ---------------------------------------------------------------------------
__device__ __forceinline__ float oct_partial(uint4 u, uint4 v,
                                             const __half2* __restrict__ bh,
                                             const float* __restrict__ ww) {
    const __half2* up = (const __half2*)&u;
    const __half2* vp = (const __half2*)&v;
    const __half2 z2 = __float2half2_rn(0.f);
    float s = 0.f;
    #pragma unroll
    for (int i = 0; i < 4; i++) {
        __half2 h = __hmax2(__hadd2(__hadd2(up[i], vp[i]), bh[i]), z2);
        float2 hf = __half22float2(h);
        s = fmaf(hf.x, ww[2 * i], s);
        s = fmaf(hf.y, ww[2 * i + 1], s);
    }
    return s;
}

// ---------------------------------------------------------------------------
// Edge kernel: 32 edges per warp. Coalesced index load (lane l -> edge
// base+l), then 8 unrolled substeps x 4 edges; 8 lanes per edge gather one
// 16B chunk of u[row] and v[col] each (2 compulsory 128B lines per edge).
// ---------------------------------------------------------------------------
__global__ __launch_bounds__(256)
void edge_decode_kernel(const void* __restrict__ ei_raw,
                        const float* __restrict__ b1,
                        const float* __restrict__ W2,
                        const float* __restrict__ b2,
                        float* __restrict__ out,
                        int n_edges) {
    const int lane = threadIdx.x & 31;
    const int oct  = lane >> 3;
    const int j    = lane & 7;

    const long long base =
        (long long)((blockIdx.x * blockDim.x + threadIdx.x) >> 5) * 32;
    if (base >= n_edges) return;

    const int is64 = g_idx_is64;
    const long long* __restrict__ ei64 = (const long long*)ei_raw;
    const int*       __restrict__ ei32 = (const int*)ei_raw;

    const long long eL = base + lane;
    const bool haveL = eL < n_edges;
    int r_all, c_all;
    if (is64) {
        r_all = haveL ? (int)ei64[eL] : 0;
        c_all = haveL ? (int)ei64[(long long)n_edges + eL] : 0;
    } else {
        r_all = haveL ? ei32[eL] : 0;
        c_all = haveL ? ei32[(long long)n_edges + eL] : 0;
    }

    __half2 bh[4];
    float ww[8];
    #pragma unroll
    for (int i = 0; i < 4; i++)
        bh[i] = __floats2half2_rn(b1[8 * j + 2 * i], b1[8 * j + 2 * i + 1]);
    #pragma unroll
    for (int i = 0; i < 8; i++) ww[i] = W2[8 * j + i];
    const float bias2 = b2[0];

    const bool full_tile = (base + 32) <= (long long)n_edges;

    #pragma unroll
    for (int s = 0; s < 8; s++) {
        const int e_off = s * 4 + oct;
        const int r = __shfl_sync(0xffffffffu, r_all, e_off);
        const int c = __shfl_sync(0xffffffffu, c_all, e_off);

        const uint4 u = g_u[(size_t)r * 8 + j];
        const uint4 v = g_v[(size_t)c * 8 + j];

        float acc = oct_partial(u, v, bh, ww);
        acc += __shfl_xor_sync(0xffffffffu, acc, 1);
        acc += __shfl_xor_sync(0xffffffffu, acc, 2);
        acc += __shfl_xor_sync(0xffffffffu, acc, 4);

        if (j == 0) {
            const long long e = base + e_off;
            if (full_tile || e < n_edges) out[e] = acc + bias2;
        }
    }
}

// ---------------------------------------------------------------------------
// Launch. Inputs: z, edge_index [2,E], W1, b1, W2, b2. Output: f32 [E,1].
// ---------------------------------------------------------------------------
extern "C" void kernel_launch(void* const* d_in, const int* in_sizes, int n_in,
                              void* d_out, int out_size) {
    const float* z  = (const float*)d_in[0];
    const void*  ei = d_in[1];
    const float* W1 = (const float*)d_in[2];
    const float* b1 = (const float*)d_in[3];
    const float* W2 = (const float*)d_in[4];
    const float* b2 = (const float*)d_in[5];
    float* out = (float*)d_out;

    const int n_nodes = in_sizes[0] / HIDDEN;
    const int n_edges = in_sizes[1] / 2;

    // Phase 1: per-node fp16 projections (+ dtype detect in block 0).
    {
        const int threads = 256;
        const int blocks = (n_nodes + threads - 1) / threads;
        precompute_uv_kernel<<<blocks, threads>>>(z, W1, (const int*)ei, n_nodes);
    }

    // Phase 2: edge decode. 8 warps/block, 32 edges/warp.
    {
        const int threads = 256;
        const int edges_per_block = 256;
        const int blocks = (n_edges + edges_per_block - 1) / edges_per_block;
        edge_decode_kernel<<<blocks, threads>>>(ei, b1, W2, b2, out, n_edges);
    }
}